// round 4
// baseline (speedup 1.0000x reference)
#include <cuda_runtime.h>
#include <cstdint>

#define LC 1024
#define CS 768
#define NH 16
#define DH 48
#define CP 128

typedef unsigned long long ull;

// ---- scratch (device globals) ----
__device__ float g_Q[LC * CS];
__device__ float g_K[LC * CS];
__device__ float g_V[LC * CS];
__device__ float g_gate[LC * CS];
__device__ float g_ctx[LC * CS];
__device__ float g_attn_fallback[NH * LC * LC];
__device__ float g_pm[NH * LC * 8];    // per (h,row,jtile) tile max
__device__ float g_ps[NH * LC * 8];    // per (h,row,jtile) tile sum of exp(x - tilemax)
__device__ float g_m[NH * LC];         // row max
__device__ float g_sinv[NH * LC];      // 1/rowsum
__device__ int   g_mask_is_u8;

// ---- f32x2 helpers ----
__device__ __forceinline__ ull ffma2(ull a, ull b, ull c) {
    ull d;
    asm("fma.rn.f32x2 %0,%1,%2,%3;" : "=l"(d) : "l"(a), "l"(b), "l"(c));
    return d;
}
__device__ __forceinline__ ull pack2(float lo, float hi) {
    ull r;
    asm("mov.b64 %0,{%1,%2};" : "=l"(r) : "f"(lo), "f"(hi));
    return r;
}
__device__ __forceinline__ void unpack2(ull v, float& lo, float& hi) {
    asm("mov.b64 {%0,%1},%2;" : "=f"(lo), "=f"(hi) : "l"(v));
}

// =====================================================================
// K0: mask dtype detector
// =====================================================================
__global__ void k_detect(const unsigned int* __restrict__ m)
{
    __shared__ int s;
    if (threadIdx.x == 0) s = 0;
    __syncthreads();
    int bad = 0;
    for (int i = threadIdx.x; i < 1024; i += blockDim.x)
        if (m[i] > 1u) bad = 1;
    if (bad) atomicOr(&s, 1);
    __syncthreads();
    if (threadIdx.x == 0) g_mask_is_u8 = s;
}

// =====================================================================
// K1: fused projections. tile 64x128, 128 thr (16tx x 8ty), micro 8x8.
// cols contiguous per thread (tx*8+j) -> LDS.128 b-loads, float4 stores.
// =====================================================================
__global__ void __launch_bounds__(128, 4) k_proj(
    const float* __restrict__ S,
    const float* __restrict__ Wq, const float* __restrict__ bq,
    const float* __restrict__ Wk, const float* __restrict__ bk,
    const float* __restrict__ Wv, const float* __restrict__ bv,
    const float* __restrict__ Wg, const float* __restrict__ bg)
{
    __shared__ __align__(16) float  As[16 * 64];    // [kk][m]
    __shared__ __align__(16) float2 Bs[16 * 128];   // [kk][n] duplicated

    int bn = blockIdx.x;
    int wi = bn / 6;
    int n0 = (bn % 6) * 128;
    int m0 = blockIdx.y * 64;

    const float* W   = wi == 0 ? Wq : wi == 1 ? Wk : wi == 2 ? Wv : Wg;
    const float* bb  = wi == 0 ? bq : wi == 1 ? bk : wi == 2 ? bv : bg;
    float*       dst = wi == 0 ? g_Q : wi == 1 ? g_K : wi == 2 ? g_V : g_gate;

    int t = threadIdx.x, tx = t & 15, ty = t >> 4;

    ull acc[4][8];
#pragma unroll
    for (int p = 0; p < 4; p++)
#pragma unroll
        for (int j = 0; j < 8; j++) acc[p][j] = 0ull;

    for (int k0 = 0; k0 < CS; k0 += 16) {
#pragma unroll
        for (int l = 0; l < 2; l++) {
            int idx = l * 128 + t, row = idx >> 2, q = idx & 3;
            float4 v = *(const float4*)(S + (size_t)(m0 + row) * CS + k0 + q * 4);
            As[(q * 4 + 0) * 64 + row] = v.x;
            As[(q * 4 + 1) * 64 + row] = v.y;
            As[(q * 4 + 2) * 64 + row] = v.z;
            As[(q * 4 + 3) * 64 + row] = v.w;
        }
#pragma unroll
        for (int l = 0; l < 4; l++) {
            int idx = l * 128 + t, kk = idx >> 5, q = idx & 31;
            float4 v = *(const float4*)(W + (size_t)(k0 + kk) * CS + n0 + q * 4);
            Bs[kk * 128 + q * 4 + 0] = make_float2(v.x, v.x);
            Bs[kk * 128 + q * 4 + 1] = make_float2(v.y, v.y);
            Bs[kk * 128 + q * 4 + 2] = make_float2(v.z, v.z);
            Bs[kk * 128 + q * 4 + 3] = make_float2(v.w, v.w);
        }
        __syncthreads();
#pragma unroll
        for (int kk = 0; kk < 16; kk++) {
            const ulonglong2* Ap2 = (const ulonglong2*)(As + kk * 64);
            const ulonglong2* Bp2 = (const ulonglong2*)(Bs + kk * 128);
            ulonglong2 av0 = Ap2[ty * 2 + 0], av1 = Ap2[ty * 2 + 1];
            ull a2[4] = {av0.x, av0.y, av1.x, av1.y};
            ull b2[8];
#pragma unroll
            for (int jp = 0; jp < 4; jp++) {
                ulonglong2 bv = Bp2[tx * 4 + jp];
                b2[2 * jp] = bv.x; b2[2 * jp + 1] = bv.y;
            }
#pragma unroll
            for (int p = 0; p < 4; p++)
#pragma unroll
                for (int j = 0; j < 8; j++) acc[p][j] = ffma2(a2[p], b2[j], acc[p][j]);
        }
        __syncthreads();
    }

    float4 bi0 = *(const float4*)(bb + n0 + tx * 8);
    float4 bi1 = *(const float4*)(bb + n0 + tx * 8 + 4);
    float bias8[8] = {bi0.x, bi0.y, bi0.z, bi0.w, bi1.x, bi1.y, bi1.z, bi1.w};

#pragma unroll
    for (int p = 0; p < 4; p++) {
        float f0[8], f1[8];
#pragma unroll
        for (int j = 0; j < 8; j++) {
            float lo, hi;
            unpack2(acc[p][j], lo, hi);
            f0[j] = lo + bias8[j];
            f1[j] = hi + bias8[j];
            if (wi == 3) {
                f0[j] = 1.f / (1.f + __expf(-f0[j]));
                f1[j] = 1.f / (1.f + __expf(-f1[j]));
            }
        }
        int row = m0 + ty * 8 + 2 * p;
        float* D0 = dst + (size_t)row * CS + n0 + tx * 8;
        float* D1 = D0 + CS;
        ((float4*)D0)[0] = make_float4(f0[0], f0[1], f0[2], f0[3]);
        ((float4*)D0)[1] = make_float4(f0[4], f0[5], f0[6], f0[7]);
        ((float4*)D1)[0] = make_float4(f1[0], f1[1], f1[2], f1[3]);
        ((float4*)D1)[1] = make_float4(f1[4], f1[5], f1[6], f1[7]);
    }
}

// =====================================================================
// K2: base logits = z@Wz + dist + prior, masked, layout [h][i][j]
// =====================================================================
__global__ void __launch_bounds__(128) k_pairbias(
    const float* __restrict__ z, const void* __restrict__ maskp,
    const float* __restrict__ dist, const float* __restrict__ prior,
    const float* __restrict__ Wz, float* __restrict__ A)
{
    __shared__ __align__(16) float2 w2[128 * 8];
    __shared__ float tr[16][128];

    int i = blockIdx.x, jt = blockIdx.y;
    int t = threadIdx.x;
    int j = jt * 128 + t;

    {
        const float4* wz4 = (const float4*)(Wz + t * 16);
        float4 a = wz4[0], b = wz4[1], c = wz4[2], d = wz4[3];
        w2[t * 8 + 0] = make_float2(a.x, a.y);
        w2[t * 8 + 1] = make_float2(a.z, a.w);
        w2[t * 8 + 2] = make_float2(b.x, b.y);
        w2[t * 8 + 3] = make_float2(b.z, b.w);
        w2[t * 8 + 4] = make_float2(c.x, c.y);
        w2[t * 8 + 5] = make_float2(c.z, c.w);
        w2[t * 8 + 6] = make_float2(d.x, d.y);
        w2[t * 8 + 7] = make_float2(d.z, d.w);
    }
    __syncthreads();

    ull acc[8];
#pragma unroll
    for (int hp = 0; hp < 8; hp++) acc[hp] = 0ull;

    const float4* zp = (const float4*)(z + ((size_t)i * LC + j) * CP);
    const ull* wp = (const ull*)w2;
#pragma unroll 8
    for (int c4 = 0; c4 < 32; c4++) {
        float4 v = zp[c4];
        float vs[4] = {v.x, v.y, v.z, v.w};
#pragma unroll
        for (int u = 0; u < 4; u++) {
            ull zz = pack2(vs[u], vs[u]);
            const ull* wrow = wp + (c4 * 4 + u) * 8;
#pragma unroll
            for (int hp = 0; hp < 8; hp++) acc[hp] = ffma2(zz, wrow[hp], acc[hp]);
        }
    }

    int ij = i * LC + j;
    float bias[16];
#pragma unroll
    for (int hp = 0; hp < 8; hp++) unpack2(acc[hp], bias[2 * hp], bias[2 * hp + 1]);

    const float4* dv = (const float4*)(dist + (size_t)ij * 16);
    float4 d0 = dv[0], d1 = dv[1], d2 = dv[2], d3 = dv[3];
    float db[16] = {d0.x, d0.y, d0.z, d0.w, d1.x, d1.y, d1.z, d1.w,
                    d2.x, d2.y, d2.z, d2.w, d3.x, d3.y, d3.z, d3.w};
    float pr = prior[ij];

    bool mv;
    if (g_mask_is_u8)
        mv = ((const unsigned char*)maskp)[ij] != 0;
    else
        mv = ((const int*)maskp)[ij] != 0;

#pragma unroll
    for (int hh = 0; hh < 16; hh++) {
        float vv = bias[hh] + db[hh] + pr;
        tr[hh][t] = mv ? vv : -1e30f;
    }
    __syncthreads();
#pragma unroll
    for (int hh = 0; hh < 16; hh++)
        A[((size_t)hh * LC + i) * LC + jt * 128 + t] = tr[hh][t];
}

// =====================================================================
// K3: logits += scale*QK^T, then per-tile softmax partials (max, sumexp)
// tile 128x128, 256 thr (16tx x 16ty), micro 8x8, cols contiguous.
// =====================================================================
#define QK_SCALE 0.14433756729740643f   // 1/sqrt(48)

__global__ void __launch_bounds__(256, 2) k_qk(float* __restrict__ A)
{
    extern __shared__ __align__(16) float sm_qk[];
    float*  Qs = sm_qk;                       // [48][128]
    float2* Ks = (float2*)(sm_qk + 48 * 128); // [48][128] dup

    int jb = blockIdx.x;
    int j0 = jb * 128, i0 = blockIdx.y * 128, h = blockIdx.z;
    int t = threadIdx.x, tx = t & 15, ty = t >> 4;

#pragma unroll
    for (int l = 0; l < 6; l++) {
        int idx = l * 256 + t;
        int row = idx / 12, q = idx - row * 12;
        float4 v = *(const float4*)(g_Q + (size_t)(i0 + row) * CS + h * DH + q * 4);
        Qs[(q * 4 + 0) * 128 + row] = v.x * QK_SCALE;
        Qs[(q * 4 + 1) * 128 + row] = v.y * QK_SCALE;
        Qs[(q * 4 + 2) * 128 + row] = v.z * QK_SCALE;
        Qs[(q * 4 + 3) * 128 + row] = v.w * QK_SCALE;
        float4 w = *(const float4*)(g_K + (size_t)(j0 + row) * CS + h * DH + q * 4);
        Ks[(q * 4 + 0) * 128 + row] = make_float2(w.x, w.x);
        Ks[(q * 4 + 1) * 128 + row] = make_float2(w.y, w.y);
        Ks[(q * 4 + 2) * 128 + row] = make_float2(w.z, w.z);
        Ks[(q * 4 + 3) * 128 + row] = make_float2(w.w, w.w);
    }
    __syncthreads();

    ull acc[4][8];
#pragma unroll
    for (int p = 0; p < 4; p++)
#pragma unroll
        for (int j = 0; j < 8; j++) acc[p][j] = 0ull;

#pragma unroll 8
    for (int kk = 0; kk < 48; kk++) {
        const ulonglong2* Ap2 = (const ulonglong2*)(Qs + kk * 128);
        const ulonglong2* Bp2 = (const ulonglong2*)(Ks + kk * 128);
        ulonglong2 av0 = Ap2[ty * 2 + 0], av1 = Ap2[ty * 2 + 1];
        ull a2[4] = {av0.x, av0.y, av1.x, av1.y};
        ull b2[8];
#pragma unroll
        for (int jp = 0; jp < 4; jp++) {
            ulonglong2 bv = Bp2[tx * 4 + jp];
            b2[2 * jp] = bv.x; b2[2 * jp + 1] = bv.y;
        }
#pragma unroll
        for (int p = 0; p < 4; p++)
#pragma unroll
            for (int j = 0; j < 8; j++) acc[p][j] = ffma2(a2[p], b2[j], acc[p][j]);
    }

    // epilogue: RMW final logits + per-row tile stats
    float rm[8], rs[8];
#pragma unroll
    for (int r = 0; r < 8; r++) { rm[r] = -3.0e38f; rs[r] = 0.f; }

#pragma unroll
    for (int p = 0; p < 4; p++) {
        int r0 = i0 + ty * 8 + 2 * p;
        float* C0 = A + ((size_t)h * LC + r0) * LC + j0 + tx * 8;
        float* C1 = C0 + LC;
        float4 c0a = ((float4*)C0)[0], c0b = ((float4*)C0)[1];
        float4 c1a = ((float4*)C1)[0], c1b = ((float4*)C1)[1];
        float f0[8] = {c0a.x, c0a.y, c0a.z, c0a.w, c0b.x, c0b.y, c0b.z, c0b.w};
        float f1[8] = {c1a.x, c1a.y, c1a.z, c1a.w, c1b.x, c1b.y, c1b.z, c1b.w};
#pragma unroll
        for (int j = 0; j < 8; j++) {
            float lo, hi;
            unpack2(acc[p][j], lo, hi);
            f0[j] += lo;
            f1[j] += hi;
            rm[2 * p]     = fmaxf(rm[2 * p], f0[j]);
            rm[2 * p + 1] = fmaxf(rm[2 * p + 1], f1[j]);
            acc[p][j] = pack2(f0[j], f1[j]);     // keep finals for sum pass
        }
        ((float4*)C0)[0] = make_float4(f0[0], f0[1], f0[2], f0[3]);
        ((float4*)C0)[1] = make_float4(f0[4], f0[5], f0[6], f0[7]);
        ((float4*)C1)[0] = make_float4(f1[0], f1[1], f1[2], f1[3]);
        ((float4*)C1)[1] = make_float4(f1[4], f1[5], f1[6], f1[7]);
    }

    // reduce max across tx (lane bits 0..3)
#pragma unroll
    for (int r = 0; r < 8; r++) {
#pragma unroll
        for (int o = 1; o < 16; o <<= 1)
            rm[r] = fmaxf(rm[r], __shfl_xor_sync(0xffffffffu, rm[r], o));
    }
    // per-thread sums of exp(x - tilemax)
#pragma unroll
    for (int p = 0; p < 4; p++)
#pragma unroll
        for (int j = 0; j < 8; j++) {
            float lo, hi;
            unpack2(acc[p][j], lo, hi);
            rs[2 * p]     += __expf(lo - rm[2 * p]);
            rs[2 * p + 1] += __expf(hi - rm[2 * p + 1]);
        }
#pragma unroll
    for (int r = 0; r < 8; r++) {
#pragma unroll
        for (int o = 1; o < 16; o <<= 1)
            rs[r] += __shfl_xor_sync(0xffffffffu, rs[r], o);
    }

    if (tx == 0) {
#pragma unroll
        for (int r = 0; r < 8; r++) {
            size_t row = (size_t)h * LC + i0 + ty * 8 + r;
            g_pm[row * 8 + jb] = rm[r];
            g_ps[row * 8 + jb] = rs[r];
        }
    }
}

// =====================================================================
// K3b: combine 8 tile partials -> row max + 1/rowsum
// =====================================================================
__global__ void k_rowstat()
{
    int r = blockIdx.x * blockDim.x + threadIdx.x;
    if (r >= NH * LC) return;
    float pm[8], m = -3.0e38f;
#pragma unroll
    for (int tIdx = 0; tIdx < 8; tIdx++) {
        pm[tIdx] = g_pm[(size_t)r * 8 + tIdx];
        m = fmaxf(m, pm[tIdx]);
    }
    float s = 0.f;
#pragma unroll
    for (int tIdx = 0; tIdx < 8; tIdx++)
        s += g_ps[(size_t)r * 8 + tIdx] * __expf(pm[tIdx] - m);
    g_m[r] = m;
    g_sinv[r] = 1.f / s;
}

// =====================================================================
// K4: normalize (p = exp(x-m)/s), write attn, and ctx = p @ V.
// tile 64 rows, 128 thr (16tx x 8ty), micro 8 rows x 3 cols
// =====================================================================
__global__ void __launch_bounds__(128) k_av2(float* __restrict__ A)
{
    __shared__ __align__(16) float  As[32 * 64];   // [j][i]
    __shared__ __align__(16) float2 Vs[32 * 48];   // [j][d] dup
    __shared__ float Ms[64], Ss[64];

    int i0 = blockIdx.x * 64, h = blockIdx.y;
    int t = threadIdx.x, tx = t & 15, ty = t >> 4;

    if (t < 64) {
        Ms[t] = g_m[(size_t)h * LC + i0 + t];
        Ss[t] = g_sinv[(size_t)h * LC + i0 + t];
    }
    __syncthreads();

    ull acc[4][3];
#pragma unroll
    for (int p = 0; p < 4; p++)
#pragma unroll
        for (int c = 0; c < 3; c++) acc[p][c] = 0ull;

    for (int j0 = 0; j0 < LC; j0 += 32) {
#pragma unroll
        for (int l = 0; l < 4; l++) {
            int idx = l * 128 + t, row = idx >> 3, q = idx & 7;
            float* Ap = A + ((size_t)h * LC + i0 + row) * LC + j0 + q * 4;
            float4 v = *(const float4*)Ap;
            float m = Ms[row], si = Ss[row];
            v.x = __expf(v.x - m) * si;
            v.y = __expf(v.y - m) * si;
            v.z = __expf(v.z - m) * si;
            v.w = __expf(v.w - m) * si;
            *(float4*)Ap = v;              // final attn output
            As[(q * 4 + 0) * 64 + row] = v.x;
            As[(q * 4 + 1) * 64 + row] = v.y;
            As[(q * 4 + 2) * 64 + row] = v.z;
            As[(q * 4 + 3) * 64 + row] = v.w;
        }
#pragma unroll
        for (int l = 0; l < 3; l++) {
            int idx = l * 128 + t;
            int jj = idx / 12, q = idx - jj * 12;
            float4 v = *(const float4*)(g_V + (size_t)(j0 + jj) * CS + h * DH + q * 4);
            Vs[jj * 48 + q * 4 + 0] = make_float2(v.x, v.x);
            Vs[jj * 48 + q * 4 + 1] = make_float2(v.y, v.y);
            Vs[jj * 48 + q * 4 + 2] = make_float2(v.z, v.z);
            Vs[jj * 48 + q * 4 + 3] = make_float2(v.w, v.w);
        }
        __syncthreads();
#pragma unroll
        for (int kk = 0; kk < 32; kk++) {
            const ull* Ap = (const ull*)(As + kk * 64);
            const ull* Vp = (const ull*)(Vs + kk * 48);
            ull a2[4], b2[3];
#pragma unroll
            for (int p = 0; p < 4; p++) a2[p] = Ap[ty * 4 + p];
#pragma unroll
            for (int c = 0; c < 3; c++) b2[c] = Vp[tx * 3 + c];
#pragma unroll
            for (int p = 0; p < 4; p++)
#pragma unroll
                for (int c = 0; c < 3; c++) acc[p][c] = ffma2(a2[p], b2[c], acc[p][c]);
        }
        __syncthreads();
    }

#pragma unroll
    for (int p = 0; p < 4; p++) {
        int r = i0 + ty * 8 + 2 * p;
#pragma unroll
        for (int c = 0; c < 3; c++) {
            float lo, hi;
            unpack2(acc[p][c], lo, hi);
            g_ctx[(size_t)r * CS + h * DH + tx * 3 + c]       = lo;
            g_ctx[(size_t)(r + 1) * CS + h * DH + tx * 3 + c] = hi;
        }
    }
}

// =====================================================================
// K5: y = gate * (ctx @ Wo + bo). tile 64x64, 128 thr, micro 8x4,
// cols contiguous (tx*4+c)
// =====================================================================
__global__ void __launch_bounds__(128, 4) k_out(
    const float* __restrict__ Wo, const float* __restrict__ bo, float* __restrict__ Y)
{
    __shared__ __align__(16) float  As[16 * 64];
    __shared__ __align__(16) float2 Bs[16 * 64];

    int n0 = blockIdx.x * 64;
    int m0 = blockIdx.y * 64;
    int t = threadIdx.x, tx = t & 15, ty = t >> 4;

    ull acc[4][4];
#pragma unroll
    for (int p = 0; p < 4; p++)
#pragma unroll
        for (int c = 0; c < 4; c++) acc[p][c] = 0ull;

    for (int k0 = 0; k0 < CS; k0 += 16) {
#pragma unroll
        for (int l = 0; l < 2; l++) {
            int idx = l * 128 + t, row = idx >> 2, q = idx & 3;
            float4 v = *(const float4*)(g_ctx + (size_t)(m0 + row) * CS + k0 + q * 4);
            As[(q * 4 + 0) * 64 + row] = v.x;
            As[(q * 4 + 1) * 64 + row] = v.y;
            As[(q * 4 + 2) * 64 + row] = v.z;
            As[(q * 4 + 3) * 64 + row] = v.w;
        }
#pragma unroll
        for (int l = 0; l < 2; l++) {
            int idx = l * 128 + t, kk = idx >> 4, q = idx & 15;
            float4 v = *(const float4*)(Wo + (size_t)(k0 + kk) * CS + n0 + q * 4);
            Bs[kk * 64 + q * 4 + 0] = make_float2(v.x, v.x);
            Bs[kk * 64 + q * 4 + 1] = make_float2(v.y, v.y);
            Bs[kk * 64 + q * 4 + 2] = make_float2(v.z, v.z);
            Bs[kk * 64 + q * 4 + 3] = make_float2(v.w, v.w);
        }
        __syncthreads();
#pragma unroll
        for (int kk = 0; kk < 16; kk++) {
            const ulonglong2* Ap2 = (const ulonglong2*)(As + kk * 64);
            const ulonglong2* Bp2 = (const ulonglong2*)(Bs + kk * 64);
            ulonglong2 av0 = Ap2[ty * 2 + 0], av1 = Ap2[ty * 2 + 1];
            ull a2[4] = {av0.x, av0.y, av1.x, av1.y};
            ull b2[4];
#pragma unroll
            for (int cp = 0; cp < 2; cp++) {
                ulonglong2 bv = Bp2[tx * 2 + cp];
                b2[2 * cp] = bv.x; b2[2 * cp + 1] = bv.y;
            }
#pragma unroll
            for (int p = 0; p < 4; p++)
#pragma unroll
                for (int c = 0; c < 4; c++) acc[p][c] = ffma2(a2[p], b2[c], acc[p][c]);
        }
        __syncthreads();
    }

    float4 bi = *(const float4*)(bo + n0 + tx * 4);
    float bias4[4] = {bi.x, bi.y, bi.z, bi.w};

#pragma unroll
    for (int p = 0; p < 4; p++) {
        int row = m0 + ty * 8 + 2 * p;
        float4 g0 = *(const float4*)(g_gate + (size_t)row * CS + n0 + tx * 4);
        float4 g1 = *(const float4*)(g_gate + (size_t)(row + 1) * CS + n0 + tx * 4);
        float f0[4], f1[4];
#pragma unroll
        for (int c = 0; c < 4; c++) {
            float lo, hi;
            unpack2(acc[p][c], lo, hi);
            f0[c] = lo + bias4[c];
            f1[c] = hi + bias4[c];
        }
        *(float4*)(Y + (size_t)row * CS + n0 + tx * 4) =
            make_float4(f0[0] * g0.x, f0[1] * g0.y, f0[2] * g0.z, f0[3] * g0.w);
        *(float4*)(Y + (size_t)(row + 1) * CS + n0 + tx * 4) =
            make_float4(f1[0] * g1.x, f1[1] * g1.y, f1[2] * g1.z, f1[3] * g1.w);
    }
}

// =====================================================================
extern "C" void kernel_launch(void* const* d_in, const int* in_sizes, int n_in,
                              void* d_out, int out_size)
{
    const float* s     = (const float*)d_in[0];
    const float* z     = (const float*)d_in[1];
    const void*  mask  = d_in[2];
    const float* dist  = (const float*)d_in[3];
    const float* prior = (const float*)d_in[4];
    const float* Wq = (const float*)d_in[5];  const float* bq = (const float*)d_in[6];
    const float* Wk = (const float*)d_in[7];  const float* bk = (const float*)d_in[8];
    const float* Wv = (const float*)d_in[9];  const float* bv = (const float*)d_in[10];
    const float* Wz = (const float*)d_in[11];
    const float* Wo = (const float*)d_in[12]; const float* bo = (const float*)d_in[13];
    const float* Wg = (const float*)d_in[14]; const float* bg = (const float*)d_in[15];

    float* Y = (float*)d_out;
    float* attn;
    if (out_size >= LC * CS + NH * LC * LC) {
        attn = (float*)d_out + LC * CS;
    } else {
        void* p = nullptr;
        cudaGetSymbolAddress(&p, g_attn_fallback);
        attn = (float*)p;
    }

    const int qk_smem = 48 * 128 * 4 + 48 * 128 * 8;   // 73728 bytes
    cudaFuncSetAttribute(k_qk, cudaFuncAttributeMaxDynamicSharedMemorySize, qk_smem);

    k_detect  <<<1, 256>>>((const unsigned int*)mask);
    k_proj    <<<dim3(24, 16),          128>>>(s, Wq, bq, Wk, bk, Wv, bv, Wg, bg);
    k_pairbias<<<dim3(LC, 8),           128>>>(z, mask, dist, prior, Wz, attn);
    k_qk      <<<dim3(8, 8, 16), 256, qk_smem>>>(attn);
    k_rowstat <<<64,                    256>>>();
    k_av2     <<<dim3(16, NH),          128>>>(attn);
    k_out     <<<dim3(12, 16),          128>>>(Wo, bo, Y);
}

// round 5
// speedup vs baseline: 1.4051x; 1.4051x over previous
#include <cuda_runtime.h>
#include <cstdint>

#define LC 1024
#define CS 768
#define NH 16
#define DH 48
#define CP 128

typedef unsigned long long ull;

// ---- scratch (device globals) ----
__device__ float g_Q[LC * CS];
__device__ float g_K[LC * CS];
__device__ float g_V[LC * CS];
__device__ float g_gate[LC * CS];
__device__ float g_ctx[LC * CS];
__device__ float g_attn_fallback[NH * LC * LC];
__device__ float g_pm[NH * LC * 16];   // per (h,row,jtile) tile max
__device__ float g_ps[NH * LC * 16];   // per (h,row,jtile) tile sumexp
__device__ float g_m[NH * LC];         // row max
__device__ float g_sinv[NH * LC];      // 1/rowsum
__device__ int   g_mask_is_u8;

// ---- f32x2 helpers ----
__device__ __forceinline__ ull ffma2(ull a, ull b, ull c) {
    ull d;
    asm("fma.rn.f32x2 %0,%1,%2,%3;" : "=l"(d) : "l"(a), "l"(b), "l"(c));
    return d;
}
__device__ __forceinline__ ull pack2(float lo, float hi) {
    ull r;
    asm("mov.b64 %0,{%1,%2};" : "=l"(r) : "f"(lo), "f"(hi));
    return r;
}
__device__ __forceinline__ void unpack2(ull v, float& lo, float& hi) {
    asm("mov.b64 {%0,%1},%2;" : "=f"(lo), "=f"(hi) : "l"(v));
}

// =====================================================================
// K0: mask dtype detector
// =====================================================================
__global__ void k_detect(const unsigned int* __restrict__ m)
{
    __shared__ int s;
    if (threadIdx.x == 0) s = 0;
    __syncthreads();
    int bad = 0;
    for (int i = threadIdx.x; i < 1024; i += blockDim.x)
        if (m[i] > 1u) bad = 1;
    if (bad) atomicOr(&s, 1);
    __syncthreads();
    if (threadIdx.x == 0) g_mask_is_u8 = s;
}

// =====================================================================
// K1: fused projections (R3 version - conflict-free LDS.64 pattern)
// tile 64x128, 128 thr (16tx x 8ty), micro 8x8
// =====================================================================
__global__ void __launch_bounds__(128) k_proj(
    const float* __restrict__ S,
    const float* __restrict__ Wq, const float* __restrict__ bq,
    const float* __restrict__ Wk, const float* __restrict__ bk,
    const float* __restrict__ Wv, const float* __restrict__ bv,
    const float* __restrict__ Wg, const float* __restrict__ bg)
{
    __shared__ __align__(16) float  As[16 * 64];    // [kk][m]
    __shared__ __align__(16) float2 Bs[16 * 128];   // [kk][n] duplicated

    int bn = blockIdx.x;
    int wi = bn / 6;
    int n0 = (bn % 6) * 128;
    int m0 = blockIdx.y * 64;

    const float* W   = wi == 0 ? Wq : wi == 1 ? Wk : wi == 2 ? Wv : Wg;
    const float* bb  = wi == 0 ? bq : wi == 1 ? bk : wi == 2 ? bv : bg;
    float*       dst = wi == 0 ? g_Q : wi == 1 ? g_K : wi == 2 ? g_V : g_gate;

    int t = threadIdx.x, tx = t & 15, ty = t >> 4;

    ull acc[4][8];
#pragma unroll
    for (int p = 0; p < 4; p++)
#pragma unroll
        for (int j = 0; j < 8; j++) acc[p][j] = 0ull;

    for (int k0 = 0; k0 < CS; k0 += 16) {
#pragma unroll
        for (int l = 0; l < 2; l++) {
            int idx = l * 128 + t, row = idx >> 2, q = idx & 3;
            float4 v = *(const float4*)(S + (size_t)(m0 + row) * CS + k0 + q * 4);
            As[(q * 4 + 0) * 64 + row] = v.x;
            As[(q * 4 + 1) * 64 + row] = v.y;
            As[(q * 4 + 2) * 64 + row] = v.z;
            As[(q * 4 + 3) * 64 + row] = v.w;
        }
#pragma unroll
        for (int l = 0; l < 4; l++) {
            int idx = l * 128 + t, kk = idx >> 5, q = idx & 31;
            float4 v = *(const float4*)(W + (size_t)(k0 + kk) * CS + n0 + q * 4);
            Bs[kk * 128 + q * 4 + 0] = make_float2(v.x, v.x);
            Bs[kk * 128 + q * 4 + 1] = make_float2(v.y, v.y);
            Bs[kk * 128 + q * 4 + 2] = make_float2(v.z, v.z);
            Bs[kk * 128 + q * 4 + 3] = make_float2(v.w, v.w);
        }
        __syncthreads();
#pragma unroll
        for (int kk = 0; kk < 16; kk++) {
            const ull* Ap = (const ull*)(As + kk * 64);
            const ull* Bp = (const ull*)(Bs + kk * 128);
            ull a2[4], b2[8];
#pragma unroll
            for (int p = 0; p < 4; p++) a2[p] = Ap[ty * 4 + p];
#pragma unroll
            for (int j = 0; j < 8; j++) b2[j] = Bp[tx + 16 * j];
#pragma unroll
            for (int p = 0; p < 4; p++)
#pragma unroll
                for (int j = 0; j < 8; j++) acc[p][j] = ffma2(a2[p], b2[j], acc[p][j]);
        }
        __syncthreads();
    }

#pragma unroll
    for (int j = 0; j < 8; j++) {
        int col = n0 + tx + 16 * j;
        float b = bb[col];
#pragma unroll
        for (int p = 0; p < 4; p++) {
            float lo, hi;
            unpack2(acc[p][j], lo, hi);
            lo += b; hi += b;
            if (wi == 3) {
                lo = 1.f / (1.f + __expf(-lo));
                hi = 1.f / (1.f + __expf(-hi));
            }
            int row = m0 + ty * 8 + 2 * p;
            dst[(size_t)row * CS + col]       = lo;
            dst[(size_t)(row + 1) * CS + col] = hi;
        }
    }
}

// =====================================================================
// K2: base logits = z@Wz + dist + prior, masked, layout [h][i][j]
// =====================================================================
__global__ void __launch_bounds__(128) k_pairbias(
    const float* __restrict__ z, const void* __restrict__ maskp,
    const float* __restrict__ dist, const float* __restrict__ prior,
    const float* __restrict__ Wz, float* __restrict__ A)
{
    __shared__ __align__(16) float2 w2[128 * 8];
    __shared__ float tr[16][128];

    int i = blockIdx.x, jt = blockIdx.y;
    int t = threadIdx.x;
    int j = jt * 128 + t;

    {
        const float4* wz4 = (const float4*)(Wz + t * 16);
        float4 a = wz4[0], b = wz4[1], c = wz4[2], d = wz4[3];
        w2[t * 8 + 0] = make_float2(a.x, a.y);
        w2[t * 8 + 1] = make_float2(a.z, a.w);
        w2[t * 8 + 2] = make_float2(b.x, b.y);
        w2[t * 8 + 3] = make_float2(b.z, b.w);
        w2[t * 8 + 4] = make_float2(c.x, c.y);
        w2[t * 8 + 5] = make_float2(c.z, c.w);
        w2[t * 8 + 6] = make_float2(d.x, d.y);
        w2[t * 8 + 7] = make_float2(d.z, d.w);
    }
    __syncthreads();

    ull acc[8];
#pragma unroll
    for (int hp = 0; hp < 8; hp++) acc[hp] = 0ull;

    const float4* zp = (const float4*)(z + ((size_t)i * LC + j) * CP);
    const ull* wp = (const ull*)w2;
#pragma unroll 8
    for (int c4 = 0; c4 < 32; c4++) {
        float4 v = zp[c4];
        float vs[4] = {v.x, v.y, v.z, v.w};
#pragma unroll
        for (int u = 0; u < 4; u++) {
            ull zz = pack2(vs[u], vs[u]);
            const ull* wrow = wp + (c4 * 4 + u) * 8;
#pragma unroll
            for (int hp = 0; hp < 8; hp++) acc[hp] = ffma2(zz, wrow[hp], acc[hp]);
        }
    }

    int ij = i * LC + j;
    float bias[16];
#pragma unroll
    for (int hp = 0; hp < 8; hp++) unpack2(acc[hp], bias[2 * hp], bias[2 * hp + 1]);

    const float4* dv = (const float4*)(dist + (size_t)ij * 16);
    float4 d0 = dv[0], d1 = dv[1], d2 = dv[2], d3 = dv[3];
    float db[16] = {d0.x, d0.y, d0.z, d0.w, d1.x, d1.y, d1.z, d1.w,
                    d2.x, d2.y, d2.z, d2.w, d3.x, d3.y, d3.z, d3.w};
    float pr = prior[ij];

    bool mv;
    if (g_mask_is_u8)
        mv = ((const unsigned char*)maskp)[ij] != 0;
    else
        mv = ((const int*)maskp)[ij] != 0;

#pragma unroll
    for (int hh = 0; hh < 16; hh++) {
        float vv = bias[hh] + db[hh] + pr;
        tr[hh][t] = mv ? vv : -1e30f;
    }
    __syncthreads();
#pragma unroll
    for (int hh = 0; hh < 16; hh++)
        A[((size_t)hh * LC + i) * LC + jt * 128 + t] = tr[hh][t];
}

// =====================================================================
// K3: logits += scale*QK^T, k-PAIRED f32x2 (lanes over K dim).
// tile 128(i) x 64(j), 256 thr (16tx x 16ty), micro 8 rows x 4 cols.
// Per k-pair: 4 LDS.128 (A, broadcast over tx) + 4 LDS.64 (B, 8B stride)
// = conflict-free, 4 FFMA2 per LDS. Fused per-tile softmax partials.
// =====================================================================
#define QK_SCALE 0.14433756729740643f   // 1/sqrt(48)

__global__ void __launch_bounds__(256, 2) k_qk(float* __restrict__ A)
{
    __shared__ __align__(16) ull Asp[24 * 128];   // [kpair][row] = (q_2kp, q_2kp+1)*scale
    __shared__ __align__(16) ull Bsp[24 * 64];    // [kpair][col] = (k_2kp, k_2kp+1)

    int jb = blockIdx.x;                  // 0..15
    int j0 = jb * 64, i0 = blockIdx.y * 128, h = blockIdx.z;
    int t = threadIdx.x, tx = t & 15, ty = t >> 4;

    // load Q tile: 128 rows x 12 float4; consecutive threads -> consecutive rows
#pragma unroll
    for (int l = 0; l < 6; l++) {
        int idx = l * 256 + t;
        int row = idx & 127, q = idx >> 7;
        float4 v = *(const float4*)(g_Q + (size_t)(i0 + row) * CS + h * DH + q * 4);
        Asp[(2 * q) * 128 + row]     = pack2(v.x * QK_SCALE, v.y * QK_SCALE);
        Asp[(2 * q + 1) * 128 + row] = pack2(v.z * QK_SCALE, v.w * QK_SCALE);
    }
    // load K tile: 64 rows x 12 float4
#pragma unroll
    for (int l = 0; l < 3; l++) {
        int idx = l * 256 + t;
        int row = idx & 63, q = idx >> 6;
        float4 v = *(const float4*)(g_K + (size_t)(j0 + row) * CS + h * DH + q * 4);
        Bsp[(2 * q) * 64 + row]     = pack2(v.x, v.y);
        Bsp[(2 * q + 1) * 64 + row] = pack2(v.z, v.w);
    }
    __syncthreads();

    ull acc[8][4];
#pragma unroll
    for (int r = 0; r < 8; r++)
#pragma unroll
        for (int j = 0; j < 4; j++) acc[r][j] = 0ull;

#pragma unroll 6
    for (int kp = 0; kp < 24; kp++) {
        const ulonglong2* Ap2 = (const ulonglong2*)(Asp + kp * 128);
        const ull* Bp = Bsp + kp * 64;
        ull b[4];
#pragma unroll
        for (int j = 0; j < 4; j++) b[j] = Bp[tx + 16 * j];
#pragma unroll
        for (int p = 0; p < 4; p++) {
            ulonglong2 av = Ap2[ty * 4 + p];   // rows ty*8+2p, ty*8+2p+1
#pragma unroll
            for (int j = 0; j < 4; j++) {
                acc[2 * p][j]     = ffma2(av.x, b[j], acc[2 * p][j]);
                acc[2 * p + 1][j] = ffma2(av.y, b[j], acc[2 * p + 1][j]);
            }
        }
    }

    // epilogue: horizontal add, RMW final logits, tile stats
    float fres[8][4];
    float rm[8], rs[8];
#pragma unroll
    for (int r = 0; r < 8; r++) { rm[r] = -3.0e38f; rs[r] = 0.f; }

#pragma unroll
    for (int r = 0; r < 8; r++) {
        int row = i0 + ty * 8 + r;
        float* C = A + ((size_t)h * LC + row) * LC + j0;
#pragma unroll
        for (int j = 0; j < 4; j++) {
            float lo, hi;
            unpack2(acc[r][j], lo, hi);
            float f = C[tx + 16 * j] + lo + hi;
            C[tx + 16 * j] = f;
            fres[r][j] = f;
            rm[r] = fmaxf(rm[r], f);
        }
    }

#pragma unroll
    for (int r = 0; r < 8; r++) {
#pragma unroll
        for (int o = 1; o < 16; o <<= 1)
            rm[r] = fmaxf(rm[r], __shfl_xor_sync(0xffffffffu, rm[r], o));
    }
#pragma unroll
    for (int r = 0; r < 8; r++)
#pragma unroll
        for (int j = 0; j < 4; j++)
            rs[r] += __expf(fres[r][j] - rm[r]);
#pragma unroll
    for (int r = 0; r < 8; r++) {
#pragma unroll
        for (int o = 1; o < 16; o <<= 1)
            rs[r] += __shfl_xor_sync(0xffffffffu, rs[r], o);
    }

    if (tx == 0) {
#pragma unroll
        for (int r = 0; r < 8; r++) {
            size_t row = (size_t)h * LC + i0 + ty * 8 + r;
            g_pm[row * 16 + jb] = rm[r];
            g_ps[row * 16 + jb] = rs[r];
        }
    }
}

// =====================================================================
// K3b: combine 16 tile partials -> row max + 1/rowsum
// =====================================================================
__global__ void k_rowstat()
{
    int r = blockIdx.x * blockDim.x + threadIdx.x;
    if (r >= NH * LC) return;
    float pm[16], m = -3.0e38f;
#pragma unroll
    for (int tIdx = 0; tIdx < 16; tIdx++) {
        pm[tIdx] = g_pm[(size_t)r * 16 + tIdx];
        m = fmaxf(m, pm[tIdx]);
    }
    float s = 0.f;
#pragma unroll
    for (int tIdx = 0; tIdx < 16; tIdx++)
        s += g_ps[(size_t)r * 16 + tIdx] * __expf(pm[tIdx] - m);
    g_m[r] = m;
    g_sinv[r] = 1.f / s;
}

// =====================================================================
// K4: normalize (p = exp(x-m)*sinv), write attn, ctx = p @ V.
// tile 64 rows, 128 thr (16tx x 8ty), micro 8 rows x 3 cols
// =====================================================================
__global__ void __launch_bounds__(128) k_av2(float* __restrict__ A)
{
    __shared__ __align__(16) float  As[32 * 64];   // [j][i]
    __shared__ __align__(16) float2 Vs[32 * 48];   // [j][d] dup
    __shared__ float Ms[64], Ss[64];

    int i0 = blockIdx.x * 64, h = blockIdx.y;
    int t = threadIdx.x, tx = t & 15, ty = t >> 4;

    if (t < 64) {
        Ms[t] = g_m[(size_t)h * LC + i0 + t];
        Ss[t] = g_sinv[(size_t)h * LC + i0 + t];
    }
    __syncthreads();

    ull acc[4][3];
#pragma unroll
    for (int p = 0; p < 4; p++)
#pragma unroll
        for (int c = 0; c < 3; c++) acc[p][c] = 0ull;

    for (int j0 = 0; j0 < LC; j0 += 32) {
#pragma unroll
        for (int l = 0; l < 4; l++) {
            int idx = l * 128 + t, row = idx >> 3, q = idx & 7;
            float* Ap = A + ((size_t)h * LC + i0 + row) * LC + j0 + q * 4;
            float4 v = *(const float4*)Ap;
            float m = Ms[row], si = Ss[row];
            v.x = __expf(v.x - m) * si;
            v.y = __expf(v.y - m) * si;
            v.z = __expf(v.z - m) * si;
            v.w = __expf(v.w - m) * si;
            *(float4*)Ap = v;              // final attn output
            As[(q * 4 + 0) * 64 + row] = v.x;
            As[(q * 4 + 1) * 64 + row] = v.y;
            As[(q * 4 + 2) * 64 + row] = v.z;
            As[(q * 4 + 3) * 64 + row] = v.w;
        }
#pragma unroll
        for (int l = 0; l < 3; l++) {
            int idx = l * 128 + t;
            int jj = idx / 12, q = idx - jj * 12;
            float4 v = *(const float4*)(g_V + (size_t)(j0 + jj) * CS + h * DH + q * 4);
            Vs[jj * 48 + q * 4 + 0] = make_float2(v.x, v.x);
            Vs[jj * 48 + q * 4 + 1] = make_float2(v.y, v.y);
            Vs[jj * 48 + q * 4 + 2] = make_float2(v.z, v.z);
            Vs[jj * 48 + q * 4 + 3] = make_float2(v.w, v.w);
        }
        __syncthreads();
#pragma unroll
        for (int kk = 0; kk < 32; kk++) {
            const ull* Ap = (const ull*)(As + kk * 64);
            const ull* Vp = (const ull*)(Vs + kk * 48);
            ull a2[4], b2[3];
#pragma unroll
            for (int p = 0; p < 4; p++) a2[p] = Ap[ty * 4 + p];
#pragma unroll
            for (int c = 0; c < 3; c++) b2[c] = Vp[tx * 3 + c];
#pragma unroll
            for (int p = 0; p < 4; p++)
#pragma unroll
                for (int c = 0; c < 3; c++) acc[p][c] = ffma2(a2[p], b2[c], acc[p][c]);
        }
        __syncthreads();
    }

#pragma unroll
    for (int p = 0; p < 4; p++) {
        int r = i0 + ty * 8 + 2 * p;
#pragma unroll
        for (int c = 0; c < 3; c++) {
            float lo, hi;
            unpack2(acc[p][c], lo, hi);
            g_ctx[(size_t)r * CS + h * DH + tx * 3 + c]       = lo;
            g_ctx[(size_t)(r + 1) * CS + h * DH + tx * 3 + c] = hi;
        }
    }
}

// =====================================================================
// K5: y = gate * (ctx @ Wo + bo)  (R3 version)
// tile 64x64, 128 thr, micro 8x4
// =====================================================================
__global__ void __launch_bounds__(128) k_out(
    const float* __restrict__ Wo, const float* __restrict__ bo, float* __restrict__ Y)
{
    __shared__ __align__(16) float  As[16 * 64];
    __shared__ __align__(16) float2 Bs[16 * 64];

    int n0 = blockIdx.x * 64;
    int m0 = blockIdx.y * 64;
    int t = threadIdx.x, tx = t & 15, ty = t >> 4;

    ull acc[4][4];
#pragma unroll
    for (int p = 0; p < 4; p++)
#pragma unroll
        for (int c = 0; c < 4; c++) acc[p][c] = 0ull;

    for (int k0 = 0; k0 < CS; k0 += 16) {
#pragma unroll
        for (int l = 0; l < 2; l++) {
            int idx = l * 128 + t, row = idx >> 2, q = idx & 3;
            float4 v = *(const float4*)(g_ctx + (size_t)(m0 + row) * CS + k0 + q * 4);
            As[(q * 4 + 0) * 64 + row] = v.x;
            As[(q * 4 + 1) * 64 + row] = v.y;
            As[(q * 4 + 2) * 64 + row] = v.z;
            As[(q * 4 + 3) * 64 + row] = v.w;
        }
#pragma unroll
        for (int l = 0; l < 2; l++) {
            int idx = l * 128 + t, kk = idx >> 4, q = idx & 15;
            float4 v = *(const float4*)(Wo + (size_t)(k0 + kk) * CS + n0 + q * 4);
            Bs[kk * 64 + q * 4 + 0] = make_float2(v.x, v.x);
            Bs[kk * 64 + q * 4 + 1] = make_float2(v.y, v.y);
            Bs[kk * 64 + q * 4 + 2] = make_float2(v.z, v.z);
            Bs[kk * 64 + q * 4 + 3] = make_float2(v.w, v.w);
        }
        __syncthreads();
#pragma unroll
        for (int kk = 0; kk < 16; kk++) {
            const ull* Ap = (const ull*)(As + kk * 64);
            const ull* Bp = (const ull*)(Bs + kk * 64);
            ull a2[4], b2[4];
#pragma unroll
            for (int p = 0; p < 4; p++) a2[p] = Ap[ty * 4 + p];
#pragma unroll
            for (int c = 0; c < 4; c++) b2[c] = Bp[tx + 16 * c];
#pragma unroll
            for (int p = 0; p < 4; p++)
#pragma unroll
                for (int c = 0; c < 4; c++) acc[p][c] = ffma2(a2[p], b2[c], acc[p][c]);
        }
        __syncthreads();
    }

#pragma unroll
    for (int c = 0; c < 4; c++) {
        int col = n0 + tx + 16 * c;
        float b = bo[col];
#pragma unroll
        for (int p = 0; p < 4; p++) {
            float lo, hi;
            unpack2(acc[p][c], lo, hi);
            int row = m0 + ty * 8 + 2 * p;
            float glo = g_gate[(size_t)row * CS + col];
            float ghi = g_gate[(size_t)(row + 1) * CS + col];
            Y[(size_t)row * CS + col]       = (lo + b) * glo;
            Y[(size_t)(row + 1) * CS + col] = (hi + b) * ghi;
        }
    }
}

// =====================================================================
extern "C" void kernel_launch(void* const* d_in, const int* in_sizes, int n_in,
                              void* d_out, int out_size)
{
    const float* s     = (const float*)d_in[0];
    const float* z     = (const float*)d_in[1];
    const void*  mask  = d_in[2];
    const float* dist  = (const float*)d_in[3];
    const float* prior = (const float*)d_in[4];
    const float* Wq = (const float*)d_in[5];  const float* bq = (const float*)d_in[6];
    const float* Wk = (const float*)d_in[7];  const float* bk = (const float*)d_in[8];
    const float* Wv = (const float*)d_in[9];  const float* bv = (const float*)d_in[10];
    const float* Wz = (const float*)d_in[11];
    const float* Wo = (const float*)d_in[12]; const float* bo = (const float*)d_in[13];
    const float* Wg = (const float*)d_in[14]; const float* bg = (const float*)d_in[15];

    float* Y = (float*)d_out;
    float* attn;
    if (out_size >= LC * CS + NH * LC * LC) {
        attn = (float*)d_out + LC * CS;
    } else {
        void* p = nullptr;
        cudaGetSymbolAddress(&p, g_attn_fallback);
        attn = (float*)p;
    }

    k_detect  <<<1, 256>>>((const unsigned int*)mask);
    k_proj    <<<dim3(24, 16),   128>>>(s, Wq, bq, Wk, bk, Wv, bv, Wg, bg);
    k_pairbias<<<dim3(LC, 8),    128>>>(z, mask, dist, prior, Wz, attn);
    k_qk      <<<dim3(16, 8, 16), 256>>>(attn);
    k_rowstat <<<64,             256>>>();
    k_av2     <<<dim3(16, NH),   128>>>(attn);
    k_out     <<<dim3(12, 16),   128>>>(Wo, bo, Y);
}

// round 6
// speedup vs baseline: 1.6088x; 1.1450x over previous
#include <cuda_runtime.h>
#include <cstdint>

#define LC 1024
#define CS 768
#define NH 16
#define DH 48
#define CP 128

typedef unsigned long long ull;

// ---- scratch (device globals) ----
__device__ float g_Q[LC * CS];
__device__ float g_K[LC * CS];
__device__ float g_V[LC * CS];
__device__ float g_gate[LC * CS];
__device__ float g_ctx[LC * CS];
__device__ float g_attn_fallback[NH * LC * LC];
__device__ int   g_mask_is_u8;

// ---- f32x2 helpers ----
__device__ __forceinline__ ull ffma2(ull a, ull b, ull c) {
    ull d;
    asm("fma.rn.f32x2 %0,%1,%2,%3;" : "=l"(d) : "l"(a), "l"(b), "l"(c));
    return d;
}
__device__ __forceinline__ ull pack2(float lo, float hi) {
    ull r;
    asm("mov.b64 %0,{%1,%2};" : "=l"(r) : "f"(lo), "f"(hi));
    return r;
}
__device__ __forceinline__ void unpack2(ull v, float& lo, float& hi) {
    asm("mov.b64 {%0,%1},%2;" : "=f"(lo), "=f"(hi) : "l"(v));
}

// ---- tf32 mma helpers (3xTF32 split for fp32-grade accuracy) ----
__device__ __forceinline__ unsigned f2tf(float x) {
    unsigned r;
    asm("cvt.rna.tf32.f32 %0, %1;" : "=r"(r) : "f"(x));
    return r;
}
__device__ __forceinline__ void split_tf32(float x, unsigned& h, unsigned& l) {
    h = f2tf(x);
    l = f2tf(x - __uint_as_float(h));
}
__device__ __forceinline__ void mma_tf32(float* c, const unsigned* a, const unsigned* b) {
    asm("mma.sync.aligned.m16n8k8.row.col.f32.tf32.tf32.f32 "
        "{%0,%1,%2,%3}, {%4,%5,%6,%7}, {%8,%9}, {%0,%1,%2,%3};"
        : "+f"(c[0]), "+f"(c[1]), "+f"(c[2]), "+f"(c[3])
        : "r"(a[0]), "r"(a[1]), "r"(a[2]), "r"(a[3]), "r"(b[0]), "r"(b[1]));
}

// =====================================================================
// K0: mask dtype detector
// =====================================================================
__global__ void k_detect(const unsigned int* __restrict__ m)
{
    __shared__ int s;
    if (threadIdx.x == 0) s = 0;
    __syncthreads();
    int bad = 0;
    for (int i = threadIdx.x; i < 1024; i += blockDim.x)
        if (m[i] > 1u) bad = 1;
    if (bad) atomicOr(&s, 1);
    __syncthreads();
    if (threadIdx.x == 0) g_mask_is_u8 = s;
}

// =====================================================================
// K1: fused projections via tensor cores (tf32x3).
// block tile 128(M)x64(N), 256 thr = 8 warps (4wm x 2wn), warp 32x32.
// grid (48, 8): blockIdx.x -> {weight 0..3} x {12 n-tiles}
// =====================================================================
__global__ void __launch_bounds__(256) k_proj_tc(
    const float* __restrict__ S,
    const float* __restrict__ Wq, const float* __restrict__ bq,
    const float* __restrict__ Wk, const float* __restrict__ bk,
    const float* __restrict__ Wv, const float* __restrict__ bv,
    const float* __restrict__ Wg, const float* __restrict__ bg)
{
    __shared__ __align__(16) float As[128 * 36];   // [m][k], pad 36
    __shared__ __align__(16) float Bs[64 * 36];    // [n][k], pad 36

    int ntb = blockIdx.x;
    int wi = ntb / 12;
    int n0 = (ntb % 12) * 64;
    int m0 = blockIdx.y * 128;

    const float* W   = wi == 0 ? Wq : wi == 1 ? Wk : wi == 2 ? Wv : Wg;
    const float* bb  = wi == 0 ? bq : wi == 1 ? bk : wi == 2 ? bv : bg;
    float*       dst = wi == 0 ? g_Q : wi == 1 ? g_K : wi == 2 ? g_V : g_gate;

    int t = threadIdx.x;
    int warp = t >> 5, lane = t & 31;
    int wm = warp >> 1, wn = warp & 1;
    int g = lane >> 2, tg = lane & 3;

    float acc[2][4][4] = {};

    for (int k0 = 0; k0 < CS; k0 += 32) {
#pragma unroll
        for (int l = 0; l < 4; l++) {
            int idx = l * 256 + t, row = idx >> 3, q = idx & 7;
            float4 v = *(const float4*)(S + (size_t)(m0 + row) * CS + k0 + q * 4);
            *(float4*)(As + row * 36 + q * 4) = v;
        }
#pragma unroll
        for (int l = 0; l < 2; l++) {
            int idx = l * 256 + t, kk = idx >> 4, q = idx & 15;
            float4 v = *(const float4*)(W + (size_t)(k0 + kk) * CS + n0 + q * 4);
            Bs[(q * 4 + 0) * 36 + kk] = v.x;
            Bs[(q * 4 + 1) * 36 + kk] = v.y;
            Bs[(q * 4 + 2) * 36 + kk] = v.z;
            Bs[(q * 4 + 3) * 36 + kk] = v.w;
        }
        __syncthreads();

#pragma unroll
        for (int ks = 0; ks < 4; ks++) {
            int kb = ks * 8;
            unsigned bh[4][2], bl[4][2];
#pragma unroll
            for (int nt = 0; nt < 4; nt++) {
#pragma unroll
                for (int e = 0; e < 2; e++) {
                    float v = Bs[(wn * 32 + nt * 8 + g) * 36 + kb + tg + 4 * e];
                    split_tf32(v, bh[nt][e], bl[nt][e]);
                }
            }
#pragma unroll
            for (int mt = 0; mt < 2; mt++) {
                unsigned ah[4], al[4];
                int r0 = wm * 32 + mt * 16 + g;
                float v0 = As[r0 * 36 + kb + tg];
                float v1 = As[(r0 + 8) * 36 + kb + tg];
                float v2 = As[r0 * 36 + kb + tg + 4];
                float v3 = As[(r0 + 8) * 36 + kb + tg + 4];
                split_tf32(v0, ah[0], al[0]);
                split_tf32(v1, ah[1], al[1]);
                split_tf32(v2, ah[2], al[2]);
                split_tf32(v3, ah[3], al[3]);
#pragma unroll
                for (int nt = 0; nt < 4; nt++) {
                    mma_tf32(acc[mt][nt], ah, bh[nt]);
                    mma_tf32(acc[mt][nt], ah, bl[nt]);
                    mma_tf32(acc[mt][nt], al, bh[nt]);
                }
            }
        }
        __syncthreads();
    }

#pragma unroll
    for (int mt = 0; mt < 2; mt++) {
#pragma unroll
        for (int nt = 0; nt < 4; nt++) {
            int col = n0 + wn * 32 + nt * 8 + 2 * tg;
            float b0 = bb[col], b1 = bb[col + 1];
            int r = m0 + wm * 32 + mt * 16 + g;
            float v0 = acc[mt][nt][0] + b0, v1 = acc[mt][nt][1] + b1;
            float v2 = acc[mt][nt][2] + b0, v3 = acc[mt][nt][3] + b1;
            if (wi == 3) {
                v0 = 1.f / (1.f + __expf(-v0));
                v1 = 1.f / (1.f + __expf(-v1));
                v2 = 1.f / (1.f + __expf(-v2));
                v3 = 1.f / (1.f + __expf(-v3));
            }
            *(float2*)(dst + (size_t)r * CS + col)       = make_float2(v0, v1);
            *(float2*)(dst + (size_t)(r + 8) * CS + col) = make_float2(v2, v3);
        }
    }
}

// =====================================================================
// K2: base logits = z@Wz + dist + prior, masked, layout [h][i][j]
// =====================================================================
__global__ void __launch_bounds__(128) k_pairbias(
    const float* __restrict__ z, const void* __restrict__ maskp,
    const float* __restrict__ dist, const float* __restrict__ prior,
    const float* __restrict__ Wz, float* __restrict__ A)
{
    __shared__ __align__(16) float2 w2[128 * 8];
    __shared__ float tr[16][128];

    int i = blockIdx.x, jt = blockIdx.y;
    int t = threadIdx.x;
    int j = jt * 128 + t;

    {
        const float4* wz4 = (const float4*)(Wz + t * 16);
        float4 a = wz4[0], b = wz4[1], c = wz4[2], d = wz4[3];
        w2[t * 8 + 0] = make_float2(a.x, a.y);
        w2[t * 8 + 1] = make_float2(a.z, a.w);
        w2[t * 8 + 2] = make_float2(b.x, b.y);
        w2[t * 8 + 3] = make_float2(b.z, b.w);
        w2[t * 8 + 4] = make_float2(c.x, c.y);
        w2[t * 8 + 5] = make_float2(c.z, c.w);
        w2[t * 8 + 6] = make_float2(d.x, d.y);
        w2[t * 8 + 7] = make_float2(d.z, d.w);
    }
    __syncthreads();

    ull acc[8];
#pragma unroll
    for (int hp = 0; hp < 8; hp++) acc[hp] = 0ull;

    const float4* zp = (const float4*)(z + ((size_t)i * LC + j) * CP);
    const ull* wp = (const ull*)w2;
#pragma unroll 8
    for (int c4 = 0; c4 < 32; c4++) {
        float4 v = zp[c4];
        float vs[4] = {v.x, v.y, v.z, v.w};
#pragma unroll
        for (int u = 0; u < 4; u++) {
            ull zz = pack2(vs[u], vs[u]);
            const ull* wrow = wp + (c4 * 4 + u) * 8;
#pragma unroll
            for (int hp = 0; hp < 8; hp++) acc[hp] = ffma2(zz, wrow[hp], acc[hp]);
        }
    }

    int ij = i * LC + j;
    float bias[16];
#pragma unroll
    for (int hp = 0; hp < 8; hp++) unpack2(acc[hp], bias[2 * hp], bias[2 * hp + 1]);

    const float4* dv = (const float4*)(dist + (size_t)ij * 16);
    float4 d0 = dv[0], d1 = dv[1], d2 = dv[2], d3 = dv[3];
    float db[16] = {d0.x, d0.y, d0.z, d0.w, d1.x, d1.y, d1.z, d1.w,
                    d2.x, d2.y, d2.z, d2.w, d3.x, d3.y, d3.z, d3.w};
    float pr = prior[ij];

    bool mv;
    if (g_mask_is_u8)
        mv = ((const unsigned char*)maskp)[ij] != 0;
    else
        mv = ((const int*)maskp)[ij] != 0;

#pragma unroll
    for (int hh = 0; hh < 16; hh++) {
        float vv = bias[hh] + db[hh] + pr;
        tr[hh][t] = mv ? vv : -1e30f;
    }
    __syncthreads();
#pragma unroll
    for (int hh = 0; hh < 16; hh++)
        A[((size_t)hh * LC + i) * LC + jt * 128 + t] = tr[hh][t];
}

// =====================================================================
// K3: logits += scale*QK^T, k-paired f32x2 (R5 scheme, stats stripped)
// tile 128(i) x 64(j), 256 thr (16tx x 16ty), micro 8 rows x 4 cols
// =====================================================================
#define QK_SCALE 0.14433756729740643f   // 1/sqrt(48)

__global__ void __launch_bounds__(256, 2) k_qk(float* __restrict__ A)
{
    __shared__ __align__(16) ull Asp[24 * 128];   // [kpair][row]
    __shared__ __align__(16) ull Bsp[24 * 64];    // [kpair][col]

    int jb = blockIdx.x;
    int j0 = jb * 64, i0 = blockIdx.y * 128, h = blockIdx.z;
    int t = threadIdx.x, tx = t & 15, ty = t >> 4;

#pragma unroll
    for (int l = 0; l < 6; l++) {
        int idx = l * 256 + t;
        int row = idx & 127, q = idx >> 7;
        float4 v = *(const float4*)(g_Q + (size_t)(i0 + row) * CS + h * DH + q * 4);
        Asp[(2 * q) * 128 + row]     = pack2(v.x * QK_SCALE, v.y * QK_SCALE);
        Asp[(2 * q + 1) * 128 + row] = pack2(v.z * QK_SCALE, v.w * QK_SCALE);
    }
#pragma unroll
    for (int l = 0; l < 3; l++) {
        int idx = l * 256 + t;
        int row = idx & 63, q = idx >> 6;
        float4 v = *(const float4*)(g_K + (size_t)(j0 + row) * CS + h * DH + q * 4);
        Bsp[(2 * q) * 64 + row]     = pack2(v.x, v.y);
        Bsp[(2 * q + 1) * 64 + row] = pack2(v.z, v.w);
    }
    __syncthreads();

    ull acc[8][4];
#pragma unroll
    for (int r = 0; r < 8; r++)
#pragma unroll
        for (int j = 0; j < 4; j++) acc[r][j] = 0ull;

#pragma unroll 6
    for (int kp = 0; kp < 24; kp++) {
        const ulonglong2* Ap2 = (const ulonglong2*)(Asp + kp * 128);
        const ull* Bp = Bsp + kp * 64;
        ull b[4];
#pragma unroll
        for (int j = 0; j < 4; j++) b[j] = Bp[tx + 16 * j];
#pragma unroll
        for (int p = 0; p < 4; p++) {
            ulonglong2 av = Ap2[ty * 4 + p];
#pragma unroll
            for (int j = 0; j < 4; j++) {
                acc[2 * p][j]     = ffma2(av.x, b[j], acc[2 * p][j]);
                acc[2 * p + 1][j] = ffma2(av.y, b[j], acc[2 * p + 1][j]);
            }
        }
    }

#pragma unroll
    for (int r = 0; r < 8; r++) {
        int row = i0 + ty * 8 + r;
        float* C = A + ((size_t)h * LC + row) * LC + j0;
#pragma unroll
        for (int j = 0; j < 4; j++) {
            float lo, hi;
            unpack2(acc[r][j], lo, hi);
            C[tx + 16 * j] += lo + hi;
        }
    }
}

// =====================================================================
// K3b: rowwise softmax in place, block per (h,i) row
// =====================================================================
__global__ void __launch_bounds__(128) k_softmax(float* __restrict__ A)
{
    size_t r = blockIdx.x;
    float* row = A + r * LC;
    int t = threadIdx.x;
    float4 v0 = ((float4*)row)[2 * t], v1 = ((float4*)row)[2 * t + 1];

    float mx = fmaxf(fmaxf(fmaxf(v0.x, v0.y), fmaxf(v0.z, v0.w)),
                     fmaxf(fmaxf(v1.x, v1.y), fmaxf(v1.z, v1.w)));
#pragma unroll
    for (int o = 16; o; o >>= 1) mx = fmaxf(mx, __shfl_xor_sync(0xffffffffu, mx, o));
    __shared__ float sm[4], ss[4];
    if ((t & 31) == 0) sm[t >> 5] = mx;
    __syncthreads();
    mx = fmaxf(fmaxf(sm[0], sm[1]), fmaxf(sm[2], sm[3]));

    v0.x = __expf(v0.x - mx); v0.y = __expf(v0.y - mx);
    v0.z = __expf(v0.z - mx); v0.w = __expf(v0.w - mx);
    v1.x = __expf(v1.x - mx); v1.y = __expf(v1.y - mx);
    v1.z = __expf(v1.z - mx); v1.w = __expf(v1.w - mx);
    float s = v0.x + v0.y + v0.z + v0.w + v1.x + v1.y + v1.z + v1.w;
#pragma unroll
    for (int o = 16; o; o >>= 1) s += __shfl_xor_sync(0xffffffffu, s, o);
    if ((t & 31) == 0) ss[t >> 5] = s;
    __syncthreads();
    s = ss[0] + ss[1] + ss[2] + ss[3];

    float inv = 1.f / s;
    v0.x *= inv; v0.y *= inv; v0.z *= inv; v0.w *= inv;
    v1.x *= inv; v1.y *= inv; v1.z *= inv; v1.w *= inv;
    ((float4*)row)[2 * t] = v0;
    ((float4*)row)[2 * t + 1] = v1;
}

// =====================================================================
// K4: ctx = attn @ V per head. tile 64 rows, 128 thr, micro 8x3
// =====================================================================
__global__ void __launch_bounds__(128) k_av(const float* __restrict__ A)
{
    __shared__ __align__(16) float  As[32 * 64];
    __shared__ __align__(16) float2 Vs[32 * 48];

    int i0 = blockIdx.x * 64, h = blockIdx.y;
    int t = threadIdx.x, tx = t & 15, ty = t >> 4;

    ull acc[4][3];
#pragma unroll
    for (int p = 0; p < 4; p++)
#pragma unroll
        for (int c = 0; c < 3; c++) acc[p][c] = 0ull;

    for (int j0 = 0; j0 < LC; j0 += 32) {
#pragma unroll
        for (int l = 0; l < 4; l++) {
            int idx = l * 128 + t, row = idx >> 3, q = idx & 7;
            float4 v = *(const float4*)(A + ((size_t)h * LC + i0 + row) * LC + j0 + q * 4);
            As[(q * 4 + 0) * 64 + row] = v.x;
            As[(q * 4 + 1) * 64 + row] = v.y;
            As[(q * 4 + 2) * 64 + row] = v.z;
            As[(q * 4 + 3) * 64 + row] = v.w;
        }
#pragma unroll
        for (int l = 0; l < 3; l++) {
            int idx = l * 128 + t;
            int jj = idx / 12, q = idx - jj * 12;
            float4 v = *(const float4*)(g_V + (size_t)(j0 + jj) * CS + h * DH + q * 4);
            Vs[jj * 48 + q * 4 + 0] = make_float2(v.x, v.x);
            Vs[jj * 48 + q * 4 + 1] = make_float2(v.y, v.y);
            Vs[jj * 48 + q * 4 + 2] = make_float2(v.z, v.z);
            Vs[jj * 48 + q * 4 + 3] = make_float2(v.w, v.w);
        }
        __syncthreads();
#pragma unroll
        for (int kk = 0; kk < 32; kk++) {
            const ull* Ap = (const ull*)(As + kk * 64);
            const ull* Vp = (const ull*)(Vs + kk * 48);
            ull a2[4], b2[3];
#pragma unroll
            for (int p = 0; p < 4; p++) a2[p] = Ap[ty * 4 + p];
#pragma unroll
            for (int c = 0; c < 3; c++) b2[c] = Vp[tx * 3 + c];
#pragma unroll
            for (int p = 0; p < 4; p++)
#pragma unroll
                for (int c = 0; c < 3; c++) acc[p][c] = ffma2(a2[p], b2[c], acc[p][c]);
        }
        __syncthreads();
    }

#pragma unroll
    for (int p = 0; p < 4; p++) {
        int r = i0 + ty * 8 + 2 * p;
#pragma unroll
        for (int c = 0; c < 3; c++) {
            float lo, hi;
            unpack2(acc[p][c], lo, hi);
            g_ctx[(size_t)r * CS + h * DH + tx * 3 + c]       = lo;
            g_ctx[(size_t)(r + 1) * CS + h * DH + tx * 3 + c] = hi;
        }
    }
}

// =====================================================================
// K5: y = gate * (ctx @ Wo + bo) via tensor cores (tf32x3).
// Same structure as k_proj_tc, grid (12, 8).
// =====================================================================
__global__ void __launch_bounds__(256) k_out_tc(
    const float* __restrict__ Wo, const float* __restrict__ bo, float* __restrict__ Y)
{
    __shared__ __align__(16) float As[128 * 36];
    __shared__ __align__(16) float Bs[64 * 36];

    int n0 = blockIdx.x * 64;
    int m0 = blockIdx.y * 128;

    int t = threadIdx.x;
    int warp = t >> 5, lane = t & 31;
    int wm = warp >> 1, wn = warp & 1;
    int g = lane >> 2, tg = lane & 3;

    float acc[2][4][4] = {};

    for (int k0 = 0; k0 < CS; k0 += 32) {
#pragma unroll
        for (int l = 0; l < 4; l++) {
            int idx = l * 256 + t, row = idx >> 3, q = idx & 7;
            float4 v = *(const float4*)(g_ctx + (size_t)(m0 + row) * CS + k0 + q * 4);
            *(float4*)(As + row * 36 + q * 4) = v;
        }
#pragma unroll
        for (int l = 0; l < 2; l++) {
            int idx = l * 256 + t, kk = idx >> 4, q = idx & 15;
            float4 v = *(const float4*)(Wo + (size_t)(k0 + kk) * CS + n0 + q * 4);
            Bs[(q * 4 + 0) * 36 + kk] = v.x;
            Bs[(q * 4 + 1) * 36 + kk] = v.y;
            Bs[(q * 4 + 2) * 36 + kk] = v.z;
            Bs[(q * 4 + 3) * 36 + kk] = v.w;
        }
        __syncthreads();

#pragma unroll
        for (int ks = 0; ks < 4; ks++) {
            int kb = ks * 8;
            unsigned bh[4][2], bl[4][2];
#pragma unroll
            for (int nt = 0; nt < 4; nt++) {
#pragma unroll
                for (int e = 0; e < 2; e++) {
                    float v = Bs[(wn * 32 + nt * 8 + g) * 36 + kb + tg + 4 * e];
                    split_tf32(v, bh[nt][e], bl[nt][e]);
                }
            }
#pragma unroll
            for (int mt = 0; mt < 2; mt++) {
                unsigned ah[4], al[4];
                int r0 = wm * 32 + mt * 16 + g;
                float v0 = As[r0 * 36 + kb + tg];
                float v1 = As[(r0 + 8) * 36 + kb + tg];
                float v2 = As[r0 * 36 + kb + tg + 4];
                float v3 = As[(r0 + 8) * 36 + kb + tg + 4];
                split_tf32(v0, ah[0], al[0]);
                split_tf32(v1, ah[1], al[1]);
                split_tf32(v2, ah[2], al[2]);
                split_tf32(v3, ah[3], al[3]);
#pragma unroll
                for (int nt = 0; nt < 4; nt++) {
                    mma_tf32(acc[mt][nt], ah, bh[nt]);
                    mma_tf32(acc[mt][nt], ah, bl[nt]);
                    mma_tf32(acc[mt][nt], al, bh[nt]);
                }
            }
        }
        __syncthreads();
    }

#pragma unroll
    for (int mt = 0; mt < 2; mt++) {
#pragma unroll
        for (int nt = 0; nt < 4; nt++) {
            int col = n0 + wn * 32 + nt * 8 + 2 * tg;
            float b0 = bo[col], b1 = bo[col + 1];
            int r = m0 + wm * 32 + mt * 16 + g;
            float2 ga = *(const float2*)(g_gate + (size_t)r * CS + col);
            float2 gb = *(const float2*)(g_gate + (size_t)(r + 8) * CS + col);
            float v0 = (acc[mt][nt][0] + b0) * ga.x;
            float v1 = (acc[mt][nt][1] + b1) * ga.y;
            float v2 = (acc[mt][nt][2] + b0) * gb.x;
            float v3 = (acc[mt][nt][3] + b1) * gb.y;
            *(float2*)(Y + (size_t)r * CS + col)       = make_float2(v0, v1);
            *(float2*)(Y + (size_t)(r + 8) * CS + col) = make_float2(v2, v3);
        }
    }
}

// =====================================================================
extern "C" void kernel_launch(void* const* d_in, const int* in_sizes, int n_in,
                              void* d_out, int out_size)
{
    const float* s     = (const float*)d_in[0];
    const float* z     = (const float*)d_in[1];
    const void*  mask  = d_in[2];
    const float* dist  = (const float*)d_in[3];
    const float* prior = (const float*)d_in[4];
    const float* Wq = (const float*)d_in[5];  const float* bq = (const float*)d_in[6];
    const float* Wk = (const float*)d_in[7];  const float* bk = (const float*)d_in[8];
    const float* Wv = (const float*)d_in[9];  const float* bv = (const float*)d_in[10];
    const float* Wz = (const float*)d_in[11];
    const float* Wo = (const float*)d_in[12]; const float* bo = (const float*)d_in[13];
    const float* Wg = (const float*)d_in[14]; const float* bg = (const float*)d_in[15];

    float* Y = (float*)d_out;
    float* attn;
    if (out_size >= LC * CS + NH * LC * LC) {
        attn = (float*)d_out + LC * CS;
    } else {
        void* p = nullptr;
        cudaGetSymbolAddress(&p, g_attn_fallback);
        attn = (float*)p;
    }

    k_detect  <<<1, 256>>>((const unsigned int*)mask);
    k_proj_tc <<<dim3(48, 8),     256>>>(s, Wq, bq, Wk, bk, Wv, bv, Wg, bg);
    k_pairbias<<<dim3(LC, 8),     128>>>(z, mask, dist, prior, Wz, attn);
    k_qk      <<<dim3(16, 8, 16), 256>>>(attn);
    k_softmax <<<NH * LC,         128>>>(attn);
    k_av      <<<dim3(16, NH),    128>>>(attn);
    k_out_tc  <<<dim3(12, 8),     256>>>(Wo, bo, Y);
}